// round 1
// baseline (speedup 1.0000x reference)
#include <cuda_runtime.h>
#include <cstdint>

#define Bsz   16
#define LEN   4096
#define Dm    256
#define INNER 768
#define FORD  64
#define NFFT  8192

// ---------------- scratch (static __device__, allowed) ----------------
__device__ float  g_X [(size_t)Bsz * INNER * LEN];   // (b, e, l)  201 MB
__device__ float  g_VG[(size_t)Bsz * Dm * LEN];      // v * x1     64 MB
__device__ float  g_X0[(size_t)Bsz * Dm * LEN];      // x0 gate    64 MB
__device__ float  g_OV[(size_t)Bsz * Dm * LEN];      // gated conv 64 MB
__device__ float  g_K [(size_t)Dm * LEN];            // filter     4 MB
__device__ float2 g_KH[(size_t)Dm * NFFT];           // filter spectrum 16 MB

// ---------------- implicit filter ----------------
__global__ void filter_kernel(const float* __restrict__ w1, const float* __restrict__ b1,
                              const float* __restrict__ freq,
                              const float* __restrict__ w2, const float* __restrict__ b2,
                              const float* __restrict__ w3, const float* __restrict__ b3,
                              const float* __restrict__ w4)
{
    __shared__ float ha[FORD];
    __shared__ float hb[FORD];
    int l = blockIdx.x;
    int j = threadIdx.x;   // 64 threads

    float t  = (float)l / (float)(LEN - 1);
    float a  = 1e-4f * 2.0f * 3.14159265358979323846f * (float)l / (float)LEN;
    float z0 = t, z1 = cosf(a), z2 = -sinf(a);

    float s1 = z0 * w1[j*3+0] + z1 * w1[j*3+1] + z2 * w1[j*3+2] + b1[j];
    ha[j] = sinf(freq[j] * s1);
    __syncthreads();

    float s2 = b2[j];
    #pragma unroll 8
    for (int i = 0; i < FORD; i++) s2 += ha[i] * w2[j*FORD + i];
    hb[j] = sinf(freq[j] * s2);
    __syncthreads();

    float s3 = b3[j];
    #pragma unroll 8
    for (int i = 0; i < FORD; i++) s3 += hb[i] * w3[j*FORD + i];
    float h3 = sinf(freq[j] * s3);
    __syncthreads();
    ha[j] = h3;
    __syncthreads();

    const float min_d = -4.605170185988091f / 1.5f;   // log(0.01)/1.5
    const float max_d = -4.605170185988091f / 0.3f;   // log(0.01)/0.3
    #pragma unroll
    for (int r = 0; r < 4; r++) {
        int d = j + r * FORD;
        float s4 = 0.f;
        #pragma unroll 8
        for (int i = 0; i < FORD; i++) s4 += ha[i] * w4[d*FORD + i];
        float delta = fabsf(min_d + (max_d - min_d) * (float)d / (float)(Dm - 1));
        g_K[(size_t)d * LEN + l] = s4 * expf(-t * delta);
    }
}

// ---------------- 8192-pt Stockham complex FFT (in smem) ----------------
__device__ __forceinline__ void fft_stages(float2* buf0, float2* buf1, int tid, float sign)
{
    __syncthreads();
    float2* src = buf0;
    float2* dst = buf1;
    int half = NFFT / 2;   // 4096
    int s = 1, ls = 0;
    for (int stage = 0; stage < 13; ++stage) {
        float ang_scale = sign * 3.14159265358979323846f / (float)half;
        #pragma unroll
        for (int tt = 0; tt < 8; ++tt) {
            int idx = tid + tt * 512;        // 0..4095
            int q = idx & (s - 1);
            int p = idx >> ls;
            float2 av = src[q + s * p];
            float2 bv = src[q + s * (p + half)];
            float2 sum = make_float2(av.x + bv.x, av.y + bv.y);
            float dx = av.x - bv.x, dy = av.y - bv.y;
            float sn, cs;
            __sincosf(ang_scale * (float)p, &sn, &cs);
            float2 tw = make_float2(dx * cs - dy * sn, dx * sn + dy * cs);
            dst[q + s * (2 * p)]     = sum;
            dst[q + s * (2 * p + 1)] = tw;
        }
        __syncthreads();
        float2* tmp = src; src = dst; dst = tmp;
        half >>= 1; s <<= 1; ls++;
    }
    // 13 stages (odd) -> result lives in buf1
}

__global__ void fftk_kernel()
{
    extern __shared__ float2 sm[];
    float2* A  = sm;
    float2* Bb = sm + NFFT;
    int d = blockIdx.x;
    int tid = threadIdx.x;
    for (int i = tid; i < NFFT; i += 512) {
        float re = (i < LEN) ? g_K[(size_t)d * LEN + i] : 0.f;
        A[i] = make_float2(re, 0.f);
    }
    fft_stages(A, Bb, tid, -1.f);
    for (int i = tid; i < NFFT; i += 512)
        g_KH[(size_t)d * NFFT + i] = Bb[i];
}

// ---------------- GEMM1: x[b][e][l] = u[b][l][:] . W_in[e][:] + b_in[e] ----------------
__global__ void gemm1_kernel(const float* __restrict__ u, const float* __restrict__ Win,
                             const float* __restrict__ bin)
{
    __shared__ float As[16][68];   // [k][l]
    __shared__ float Bs[16][68];   // [k][e]
    int b  = blockIdx.z;
    int l0 = blockIdx.x * 64;
    int e0 = blockIdx.y * 64;
    int tid = threadIdx.x;         // 256
    int tx = tid & 15;             // l quad
    int ty = tid >> 4;             // e quad
    float acc[4][4];
    #pragma unroll
    for (int j = 0; j < 4; j++)
        #pragma unroll
        for (int i = 0; i < 4; i++) acc[j][i] = 0.f;

    const float* ub = u + (size_t)b * LEN * Dm;
    int li = tid >> 2;
    int kq = (tid & 3) * 4;
    for (int k0 = 0; k0 < Dm; k0 += 16) {
        float4 av = *(const float4*)&ub[(size_t)(l0 + li) * Dm + k0 + kq];
        As[kq+0][li] = av.x; As[kq+1][li] = av.y; As[kq+2][li] = av.z; As[kq+3][li] = av.w;
        float4 bv = *(const float4*)&Win[(size_t)(e0 + li) * Dm + k0 + kq];
        Bs[kq+0][li] = bv.x; Bs[kq+1][li] = bv.y; Bs[kq+2][li] = bv.z; Bs[kq+3][li] = bv.w;
        __syncthreads();
        #pragma unroll
        for (int k = 0; k < 16; ++k) {
            float4 a = *(float4*)&As[k][tx * 4];
            float4 bb = *(float4*)&Bs[k][ty * 4];
            float ar[4] = {a.x, a.y, a.z, a.w};
            float br[4] = {bb.x, bb.y, bb.z, bb.w};
            #pragma unroll
            for (int j = 0; j < 4; j++)
                #pragma unroll
                for (int i = 0; i < 4; i++)
                    acc[j][i] += br[j] * ar[i];
        }
        __syncthreads();
    }
    #pragma unroll
    for (int j = 0; j < 4; j++) {
        int e = e0 + ty * 4 + j;
        float be = bin[e];
        float4 o = make_float4(acc[j][0] + be, acc[j][1] + be, acc[j][2] + be, acc[j][3] + be);
        *(float4*)&g_X[((size_t)b * INNER + e) * LEN + l0 + tx * 4] = o;
    }
}

// ---------------- short depthwise conv + gating ----------------
__global__ void shortconv_kernel(const float* __restrict__ sw, const float* __restrict__ sb)
{
    int bd = blockIdx.x;
    int b = bd >> 8, d = bd & 255;
    const float* xr0 = &g_X[((size_t)b * INNER + d        ) * LEN];
    const float* xr1 = &g_X[((size_t)b * INNER + Dm   + d ) * LEN];
    const float* xrv = &g_X[((size_t)b * INNER + 2*Dm + d ) * LEN];
    int c0 = d, c1 = Dm + d, c2 = 2 * Dm + d;
    float w00 = sw[c0*3], w01 = sw[c0*3+1], w02 = sw[c0*3+2];
    float w10 = sw[c1*3], w11 = sw[c1*3+1], w12 = sw[c1*3+2];
    float w20 = sw[c2*3], w21 = sw[c2*3+1], w22 = sw[c2*3+2];
    float bb0 = sb[c0], bb1 = sb[c1], bb2 = sb[c2];
    float* x0o = &g_X0[((size_t)b * Dm + d) * LEN];
    float* vgo = &g_VG[((size_t)b * Dm + d) * LEN];
    for (int l = threadIdx.x; l < LEN; l += blockDim.x) {
        float a2 = (l >= 2) ? xr0[l-2] : 0.f;
        float a1 = (l >= 1) ? xr0[l-1] : 0.f;
        float a0 = xr0[l];
        float ux0 = w00*a2 + w01*a1 + w02*a0 + bb0;
        float b2v = (l >= 2) ? xr1[l-2] : 0.f;
        float b1v = (l >= 1) ? xr1[l-1] : 0.f;
        float b0v = xr1[l];
        float ux1 = w10*b2v + w11*b1v + w12*b0v + bb1;
        float c2v = (l >= 2) ? xrv[l-2] : 0.f;
        float c1v = (l >= 1) ? xrv[l-1] : 0.f;
        float c0v = xrv[l];
        float uv  = w20*c2v + w21*c1v + w22*c0v + bb2;
        x0o[l] = ux0;
        vgo[l] = uv * ux1;
    }
}

// ---------------- FFT long conv: two real channels per complex FFT ----------------
__global__ void fftconv_kernel(const float* __restrict__ fbias)
{
    extern __shared__ float2 sm[];
    float2* A  = sm;
    float2* Bb = sm + NFFT;
    int blk = blockIdx.x;                    // 2048
    int b = blk >> 7, dp = blk & 127;
    int d0 = dp * 2, d1 = d0 + 1;
    int tid = threadIdx.x;

    const float* vg0 = &g_VG[((size_t)b * Dm + d0) * LEN];
    const float* vg1 = vg0 + LEN;
    for (int i = tid; i < NFFT; i += 512) {
        float re = (i < LEN) ? vg0[i] : 0.f;
        float im = (i < LEN) ? vg1[i] : 0.f;
        A[i] = make_float2(re, im);
    }
    fft_stages(A, Bb, tid, -1.f);            // spectrum Z in Bb

    const float2* KH0 = &g_KH[(size_t)d0 * NFFT];
    const float2* KH1 = KH0 + NFFT;
    for (int i = tid; i < NFFT; i += 512) {
        int jj = (NFFT - i) & (NFFT - 1);
        float2 z1 = Bb[i], z2 = Bb[jj];
        // V0 = (Z[i] + conj(Z[N-i]))/2 ; V1 = (Z[i] - conj(Z[N-i]))/(2i)
        float2 V0 = make_float2(0.5f * (z1.x + z2.x), 0.5f * (z1.y - z2.y));
        float2 V1 = make_float2(0.5f * (z1.y + z2.y), 0.5f * (z2.x - z1.x));
        float2 k0 = KH0[i], k1 = KH1[i];
        float2 P = make_float2(V0.x * k0.x - V0.y * k0.y, V0.x * k0.y + V0.y * k0.x);
        float2 Q = make_float2(V1.x * k1.x - V1.y * k1.y, V1.x * k1.y + V1.y * k1.x);
        A[i] = make_float2(P.x - Q.y, P.y + Q.x);   // W = P + i*Q
    }
    fft_stages(A, Bb, tid, +1.f);            // y0 + i*y1 in Bb (unscaled)

    const float inv = 1.f / (float)NFFT;
    float bias0 = fbias[d0], bias1 = fbias[d1];
    float* ov0 = &g_OV[((size_t)b * Dm + d0) * LEN];
    float* ov1 = ov0 + LEN;
    const float* x00 = &g_X0[((size_t)b * Dm + d0) * LEN];
    const float* x01 = x00 + LEN;
    for (int l = tid; l < LEN; l += 512) {
        float y0 = Bb[l].x * inv;
        float y1 = Bb[l].y * inv;
        ov0[l] = (y0 + vg0[l] * bias0) * x00[l];
        ov1[l] = (y1 + vg1[l] * bias1) * x01[l];
    }
}

// ---------------- GEMM2: out[b][l][o] = OV[b][:][l] . W_out[o][:] + b_out ----------------
__global__ void gemm2_kernel(const float* __restrict__ Wout, const float* __restrict__ bout,
                             float* __restrict__ out)
{
    __shared__ float As[16][68];   // [k][l]
    __shared__ float Bs[16][68];   // [k][o]
    int b  = blockIdx.z;
    int l0 = blockIdx.x * 64;
    int o0 = blockIdx.y * 64;
    int tid = threadIdx.x;
    int tx = tid & 15;             // o quad (contiguous output dim)
    int ty = tid >> 4;             // l quad
    float acc[4][4];
    #pragma unroll
    for (int j = 0; j < 4; j++)
        #pragma unroll
        for (int i = 0; i < 4; i++) acc[j][i] = 0.f;

    int kk = tid >> 4;             // 0..15 (k row for A load)
    int lq = (tid & 15) * 4;       // l quad for A load
    int oi = tid >> 2;             // 0..63  (o row for B load)
    int kq = (tid & 3) * 4;        // k quad for B load
    for (int k0 = 0; k0 < Dm; k0 += 16) {
        float4 av = *(const float4*)&g_OV[((size_t)b * Dm + k0 + kk) * LEN + l0 + lq];
        As[kk][lq+0] = av.x; As[kk][lq+1] = av.y; As[kk][lq+2] = av.z; As[kk][lq+3] = av.w;
        float4 bv = *(const float4*)&Wout[(size_t)(o0 + oi) * Dm + k0 + kq];
        Bs[kq+0][oi] = bv.x; Bs[kq+1][oi] = bv.y; Bs[kq+2][oi] = bv.z; Bs[kq+3][oi] = bv.w;
        __syncthreads();
        #pragma unroll
        for (int k = 0; k < 16; ++k) {
            float4 ov = *(float4*)&Bs[k][tx * 4];   // o values
            float4 lv = *(float4*)&As[k][ty * 4];   // l values
            float orr[4] = {ov.x, ov.y, ov.z, ov.w};
            float lrr[4] = {lv.x, lv.y, lv.z, lv.w};
            #pragma unroll
            for (int j = 0; j < 4; j++)
                #pragma unroll
                for (int i = 0; i < 4; i++)
                    acc[j][i] += lrr[j] * orr[i];
        }
        __syncthreads();
    }
    float4 bo = *(const float4*)&bout[o0 + tx * 4];
    float bor[4] = {bo.x, bo.y, bo.z, bo.w};
    #pragma unroll
    for (int j = 0; j < 4; j++) {
        int l = l0 + ty * 4 + j;
        float4 o = make_float4(acc[j][0] + bor[0], acc[j][1] + bor[1],
                               acc[j][2] + bor[2], acc[j][3] + bor[3]);
        *(float4*)&out[((size_t)b * LEN + l) * Dm + o0 + tx * 4] = o;
    }
}

// ---------------- launch ----------------
extern "C" void kernel_launch(void* const* d_in, const int* in_sizes, int n_in,
                              void* d_out, int out_size)
{
    (void)in_sizes; (void)n_in; (void)out_size;
    const float* u       = (const float*)d_in[0];
    const float* W_in    = (const float*)d_in[1];
    const float* b_in    = (const float*)d_in[2];
    const float* short_w = (const float*)d_in[3];
    const float* short_b = (const float*)d_in[4];
    const float* mlp_w1  = (const float*)d_in[5];
    const float* mlp_b1  = (const float*)d_in[6];
    const float* freq    = (const float*)d_in[7];
    const float* mlp_w2  = (const float*)d_in[8];
    const float* mlp_b2  = (const float*)d_in[9];
    const float* mlp_w3  = (const float*)d_in[10];
    const float* mlp_b3  = (const float*)d_in[11];
    const float* mlp_w4  = (const float*)d_in[12];
    const float* fbias   = (const float*)d_in[13];
    const float* W_out   = (const float*)d_in[14];
    const float* b_out   = (const float*)d_in[15];
    float* out = (float*)d_out;

    const int FFT_SMEM = NFFT * 2 * sizeof(float2);  // 131072
    cudaFuncSetAttribute(fftk_kernel,    cudaFuncAttributeMaxDynamicSharedMemorySize, FFT_SMEM);
    cudaFuncSetAttribute(fftconv_kernel, cudaFuncAttributeMaxDynamicSharedMemorySize, FFT_SMEM);

    filter_kernel<<<LEN, FORD>>>(mlp_w1, mlp_b1, freq, mlp_w2, mlp_b2, mlp_w3, mlp_b3, mlp_w4);
    fftk_kernel<<<Dm, 512, FFT_SMEM>>>();
    gemm1_kernel<<<dim3(LEN/64, INNER/64, Bsz), 256>>>(u, W_in, b_in);
    shortconv_kernel<<<Bsz * Dm, 256>>>(short_w, short_b);
    fftconv_kernel<<<Bsz * (Dm/2), 512, FFT_SMEM>>>(fbias);
    gemm2_kernel<<<dim3(LEN/64, Dm/64, Bsz), 256>>>(W_out, b_out, out);
}

// round 2
// speedup vs baseline: 1.4064x; 1.4064x over previous
#include <cuda_runtime.h>
#include <cstdint>

#define Bsz   16
#define LEN   4096
#define Dm    256
#define INNER 768
#define FORD  64
#define NFFT  8192

// ---------------- scratch (static __device__, allowed) ----------------
__device__ float  g_X [(size_t)Bsz * INNER * LEN];   // (b, e, l)  201 MB
__device__ float  g_VG[(size_t)Bsz * Dm * LEN];      // v * x1     64 MB
__device__ float  g_X0[(size_t)Bsz * Dm * LEN];      // x0 gate    64 MB
__device__ float  g_OV[(size_t)Bsz * Dm * LEN];      // gated conv 64 MB
__device__ float  g_K [(size_t)Dm * LEN];            // filter     4 MB
__device__ float2 g_KH[(size_t)Dm * NFFT];           // filter spectrum 16 MB

// ---------------- helpers ----------------
__device__ __forceinline__ uint32_t f2tf32(float x) {
    uint32_t r;
    asm("cvt.rna.tf32.f32 %0, %1;" : "=r"(r) : "f"(x));
    return r;
}

__device__ __forceinline__ void mma_tf32(float* c, const uint32_t* a, const uint32_t* b) {
    asm volatile(
        "mma.sync.aligned.m16n8k8.row.col.f32.tf32.tf32.f32 "
        "{%0,%1,%2,%3},{%4,%5,%6,%7},{%8,%9},{%0,%1,%2,%3};"
        : "+f"(c[0]), "+f"(c[1]), "+f"(c[2]), "+f"(c[3])
        : "r"(a[0]), "r"(a[1]), "r"(a[2]), "r"(a[3]), "r"(b[0]), "r"(b[1]));
}

// ---------------- implicit filter ----------------
__global__ void filter_kernel(const float* __restrict__ w1, const float* __restrict__ b1,
                              const float* __restrict__ freq,
                              const float* __restrict__ w2, const float* __restrict__ b2,
                              const float* __restrict__ w3, const float* __restrict__ b3,
                              const float* __restrict__ w4)
{
    __shared__ float ha[FORD];
    __shared__ float hb[FORD];
    int l = blockIdx.x;
    int j = threadIdx.x;   // 64 threads

    float t  = (float)l / (float)(LEN - 1);
    float a  = 1e-4f * 2.0f * 3.14159265358979323846f * (float)l / (float)LEN;
    float z0 = t, z1 = cosf(a), z2 = -sinf(a);

    float s1 = z0 * w1[j*3+0] + z1 * w1[j*3+1] + z2 * w1[j*3+2] + b1[j];
    ha[j] = sinf(freq[j] * s1);
    __syncthreads();

    float s2 = b2[j];
    #pragma unroll 8
    for (int i = 0; i < FORD; i++) s2 += ha[i] * w2[j*FORD + i];
    hb[j] = sinf(freq[j] * s2);
    __syncthreads();

    float s3 = b3[j];
    #pragma unroll 8
    for (int i = 0; i < FORD; i++) s3 += hb[i] * w3[j*FORD + i];
    float h3 = sinf(freq[j] * s3);
    __syncthreads();
    ha[j] = h3;
    __syncthreads();

    const float min_d = -4.605170185988091f / 1.5f;   // log(0.01)/1.5
    const float max_d = -4.605170185988091f / 0.3f;   // log(0.01)/0.3
    #pragma unroll
    for (int r = 0; r < 4; r++) {
        int d = j + r * FORD;
        float s4 = 0.f;
        #pragma unroll 8
        for (int i = 0; i < FORD; i++) s4 += ha[i] * w4[d*FORD + i];
        float delta = fabsf(min_d + (max_d - min_d) * (float)d / (float)(Dm - 1));
        g_K[(size_t)d * LEN + l] = s4 * expf(-t * delta);
    }
}

// ---------------- 8192-pt Stockham complex FFT (in smem) ----------------
__device__ __forceinline__ void fft_stages(float2* buf0, float2* buf1, int tid, float sign)
{
    __syncthreads();
    float2* src = buf0;
    float2* dst = buf1;
    int half = NFFT / 2;   // 4096
    int s = 1, ls = 0;
    for (int stage = 0; stage < 13; ++stage) {
        float ang_scale = sign * 3.14159265358979323846f / (float)half;
        #pragma unroll
        for (int tt = 0; tt < 8; ++tt) {
            int idx = tid + tt * 512;        // 0..4095
            int q = idx & (s - 1);
            int p = idx >> ls;
            float2 av = src[q + s * p];
            float2 bv = src[q + s * (p + half)];
            float2 sum = make_float2(av.x + bv.x, av.y + bv.y);
            float dx = av.x - bv.x, dy = av.y - bv.y;
            float sn, cs;
            __sincosf(ang_scale * (float)p, &sn, &cs);
            float2 tw = make_float2(dx * cs - dy * sn, dx * sn + dy * cs);
            dst[q + s * (2 * p)]     = sum;
            dst[q + s * (2 * p + 1)] = tw;
        }
        __syncthreads();
        float2* tmp = src; src = dst; dst = tmp;
        half >>= 1; s <<= 1; ls++;
    }
    // 13 stages (odd) -> result lives in buf1
}

__global__ void fftk_kernel()
{
    extern __shared__ float2 sm[];
    float2* A  = sm;
    float2* Bb = sm + NFFT;
    int d = blockIdx.x;
    int tid = threadIdx.x;
    for (int i = tid; i < NFFT; i += 512) {
        float re = (i < LEN) ? g_K[(size_t)d * LEN + i] : 0.f;
        A[i] = make_float2(re, 0.f);
    }
    fft_stages(A, Bb, tid, -1.f);
    for (int i = tid; i < NFFT; i += 512)
        g_KH[(size_t)d * NFFT + i] = Bb[i];
}

// ---------------- GEMM1 (tensor cores, tf32):
//   g_X[b][e][l] = sum_k Win[e][k] * u[b][l][k] + b_in[e]
//   M = e (128-tile), N = l (128-tile), K = 256
__global__ void __launch_bounds__(256, 1)
gemm1_tc(const float* __restrict__ u, const float* __restrict__ Win,
         const float* __restrict__ bin)
{
    __shared__ uint32_t As[128][36];   // [e][k]  (stride 36: conflict-free frags, v4-alignable)
    __shared__ uint32_t Bs[128][36];   // [l][k]
    int b  = blockIdx.z;
    int e0 = blockIdx.y * 128;
    int l0 = blockIdx.x * 128;
    int tid = threadIdx.x;
    int wid = tid >> 5, lane = tid & 31;
    int wm = wid & 1;          // 0..1 -> e offset 64*wm
    int wn = wid >> 1;         // 0..3 -> l offset 32*wn
    int r = lane >> 2, c = lane & 3;

    float acc[4][4][4];
    #pragma unroll
    for (int mt = 0; mt < 4; mt++)
        #pragma unroll
        for (int nt = 0; nt < 4; nt++)
            #pragma unroll
            for (int i = 0; i < 4; i++) acc[mt][nt][i] = 0.f;

    const float* ub = u + (size_t)b * LEN * Dm;

    for (int k0 = 0; k0 < Dm; k0 += 32) {
        __syncthreads();
        #pragma unroll
        for (int i = 0; i < 4; i++) {
            int f = tid + i * 256;
            int row = f >> 3, q = f & 7;
            float4 av = *(const float4*)&Win[(size_t)(e0 + row) * Dm + k0 + q * 4];
            uint4 at = make_uint4(f2tf32(av.x), f2tf32(av.y), f2tf32(av.z), f2tf32(av.w));
            *(uint4*)&As[row][q * 4] = at;
            float4 bv = *(const float4*)&ub[(size_t)(l0 + row) * Dm + k0 + q * 4];
            uint4 bt = make_uint4(f2tf32(bv.x), f2tf32(bv.y), f2tf32(bv.z), f2tf32(bv.w));
            *(uint4*)&Bs[row][q * 4] = bt;
        }
        __syncthreads();
        #pragma unroll
        for (int kk = 0; kk < 4; kk++) {
            uint32_t af[4][4], bf[4][2];
            #pragma unroll
            for (int mt = 0; mt < 4; mt++) {
                int m = wm * 64 + mt * 16;
                af[mt][0] = As[m + r][kk * 8 + c];
                af[mt][1] = As[m + r + 8][kk * 8 + c];
                af[mt][2] = As[m + r][kk * 8 + c + 4];
                af[mt][3] = As[m + r + 8][kk * 8 + c + 4];
            }
            #pragma unroll
            for (int nt = 0; nt < 4; nt++) {
                int n = wn * 32 + nt * 8 + r;
                bf[nt][0] = Bs[n][kk * 8 + c];
                bf[nt][1] = Bs[n][kk * 8 + c + 4];
            }
            #pragma unroll
            for (int mt = 0; mt < 4; mt++)
                #pragma unroll
                for (int nt = 0; nt < 4; nt++)
                    mma_tf32(acc[mt][nt], af[mt], bf[nt]);
        }
    }

    // epilogue
    #pragma unroll
    for (int mt = 0; mt < 4; mt++) {
        int e = e0 + wm * 64 + mt * 16 + r;
        float be0 = bin[e], be8 = bin[e + 8];
        #pragma unroll
        for (int nt = 0; nt < 4; nt++) {
            int l = l0 + wn * 32 + nt * 8 + c * 2;
            float2 v0 = make_float2(acc[mt][nt][0] + be0, acc[mt][nt][1] + be0);
            float2 v1 = make_float2(acc[mt][nt][2] + be8, acc[mt][nt][3] + be8);
            *(float2*)&g_X[((size_t)b * INNER + e    ) * LEN + l] = v0;
            *(float2*)&g_X[((size_t)b * INNER + e + 8) * LEN + l] = v1;
        }
    }
}

// ---------------- short depthwise conv + gating ----------------
__global__ void shortconv_kernel(const float* __restrict__ sw, const float* __restrict__ sb)
{
    int bd = blockIdx.x;
    int b = bd >> 8, d = bd & 255;
    const float* xr0 = &g_X[((size_t)b * INNER + d        ) * LEN];
    const float* xr1 = &g_X[((size_t)b * INNER + Dm   + d ) * LEN];
    const float* xrv = &g_X[((size_t)b * INNER + 2*Dm + d ) * LEN];
    int c0 = d, c1 = Dm + d, c2 = 2 * Dm + d;
    float w00 = sw[c0*3], w01 = sw[c0*3+1], w02 = sw[c0*3+2];
    float w10 = sw[c1*3], w11 = sw[c1*3+1], w12 = sw[c1*3+2];
    float w20 = sw[c2*3], w21 = sw[c2*3+1], w22 = sw[c2*3+2];
    float bb0 = sb[c0], bb1 = sb[c1], bb2 = sb[c2];
    float* x0o = &g_X0[((size_t)b * Dm + d) * LEN];
    float* vgo = &g_VG[((size_t)b * Dm + d) * LEN];
    for (int l = threadIdx.x; l < LEN; l += blockDim.x) {
        float a2 = (l >= 2) ? xr0[l-2] : 0.f;
        float a1 = (l >= 1) ? xr0[l-1] : 0.f;
        float a0 = xr0[l];
        float ux0 = w00*a2 + w01*a1 + w02*a0 + bb0;
        float b2v = (l >= 2) ? xr1[l-2] : 0.f;
        float b1v = (l >= 1) ? xr1[l-1] : 0.f;
        float b0v = xr1[l];
        float ux1 = w10*b2v + w11*b1v + w12*b0v + bb1;
        float c2v = (l >= 2) ? xrv[l-2] : 0.f;
        float c1v = (l >= 1) ? xrv[l-1] : 0.f;
        float c0v = xrv[l];
        float uv  = w20*c2v + w21*c1v + w22*c0v + bb2;
        x0o[l] = ux0;
        vgo[l] = uv * ux1;
    }
}

// ---------------- FFT long conv: two real channels per complex FFT ----------------
__global__ void fftconv_kernel(const float* __restrict__ fbias)
{
    extern __shared__ float2 sm[];
    float2* A  = sm;
    float2* Bb = sm + NFFT;
    int blk = blockIdx.x;                    // 2048
    int b = blk >> 7, dp = blk & 127;
    int d0 = dp * 2, d1 = d0 + 1;
    int tid = threadIdx.x;

    const float* vg0 = &g_VG[((size_t)b * Dm + d0) * LEN];
    const float* vg1 = vg0 + LEN;
    for (int i = tid; i < NFFT; i += 512) {
        float re = (i < LEN) ? vg0[i] : 0.f;
        float im = (i < LEN) ? vg1[i] : 0.f;
        A[i] = make_float2(re, im);
    }
    fft_stages(A, Bb, tid, -1.f);            // spectrum Z in Bb

    const float2* KH0 = &g_KH[(size_t)d0 * NFFT];
    const float2* KH1 = KH0 + NFFT;
    for (int i = tid; i < NFFT; i += 512) {
        int jj = (NFFT - i) & (NFFT - 1);
        float2 z1 = Bb[i], z2 = Bb[jj];
        float2 V0 = make_float2(0.5f * (z1.x + z2.x), 0.5f * (z1.y - z2.y));
        float2 V1 = make_float2(0.5f * (z1.y + z2.y), 0.5f * (z2.x - z1.x));
        float2 k0 = KH0[i], k1 = KH1[i];
        float2 P = make_float2(V0.x * k0.x - V0.y * k0.y, V0.x * k0.y + V0.y * k0.x);
        float2 Q = make_float2(V1.x * k1.x - V1.y * k1.y, V1.x * k1.y + V1.y * k1.x);
        A[i] = make_float2(P.x - Q.y, P.y + Q.x);   // W = P + i*Q
    }
    fft_stages(A, Bb, tid, +1.f);            // y0 + i*y1 in Bb (unscaled)

    const float inv = 1.f / (float)NFFT;
    float bias0 = fbias[d0], bias1 = fbias[d1];
    float* ov0 = &g_OV[((size_t)b * Dm + d0) * LEN];
    float* ov1 = ov0 + LEN;
    const float* x00 = &g_X0[((size_t)b * Dm + d0) * LEN];
    const float* x01 = x00 + LEN;
    for (int l = tid; l < LEN; l += 512) {
        float y0 = Bb[l].x * inv;
        float y1 = Bb[l].y * inv;
        ov0[l] = (y0 + vg0[l] * bias0) * x00[l];
        ov1[l] = (y1 + vg1[l] * bias1) * x01[l];
    }
}

// ---------------- GEMM2 (tensor cores, tf32):
//   out[b][l][o] = sum_k g_OV[b][k][l] * Wout[o][k] + b_out[o]
//   M = l (128-tile), N = o (128-tile), K = 256
__global__ void __launch_bounds__(256, 1)
gemm2_tc(const float* __restrict__ Wout, const float* __restrict__ bout,
         float* __restrict__ out)
{
    __shared__ uint32_t As[128][36];   // [l][k]
    __shared__ uint32_t Bs[128][36];   // [o][k]
    int b  = blockIdx.z;
    int l0 = blockIdx.x * 128;
    int o0 = blockIdx.y * 128;
    int tid = threadIdx.x;
    int wid = tid >> 5, lane = tid & 31;
    int wm = wid & 1;          // l offset 64*wm
    int wn = wid >> 1;         // o offset 32*wn
    int r = lane >> 2, c = lane & 3;

    float acc[4][4][4];
    #pragma unroll
    for (int mt = 0; mt < 4; mt++)
        #pragma unroll
        for (int nt = 0; nt < 4; nt++)
            #pragma unroll
            for (int i = 0; i < 4; i++) acc[mt][nt][i] = 0.f;

    const float* ovb = &g_OV[(size_t)b * Dm * LEN];

    int ka = tid >> 3;        // 0..31  (k row for A fill)
    int fa = tid & 7;         // float4 slot
    for (int k0 = 0; k0 < Dm; k0 += 32) {
        __syncthreads();
        // A fill: transpose g_OV[k][l] -> As[l][k]
        #pragma unroll
        for (int i = 0; i < 4; i++) {
            int f = fa + i * 8;               // 0..31
            int lq = f * 4;
            float4 av = *(const float4*)&ovb[(size_t)(k0 + ka) * LEN + l0 + lq];
            As[lq + 0][ka] = f2tf32(av.x);
            As[lq + 1][ka] = f2tf32(av.y);
            As[lq + 2][ka] = f2tf32(av.z);
            As[lq + 3][ka] = f2tf32(av.w);
        }
        // B fill: Wout[o][k] row copy
        #pragma unroll
        for (int i = 0; i < 4; i++) {
            int f = tid + i * 256;
            int row = f >> 3, q = f & 7;
            float4 bv = *(const float4*)&Wout[(size_t)(o0 + row) * Dm + k0 + q * 4];
            uint4 bt = make_uint4(f2tf32(bv.x), f2tf32(bv.y), f2tf32(bv.z), f2tf32(bv.w));
            *(uint4*)&Bs[row][q * 4] = bt;
        }
        __syncthreads();
        #pragma unroll
        for (int kk = 0; kk < 4; kk++) {
            uint32_t af[4][4], bf[4][2];
            #pragma unroll
            for (int mt = 0; mt < 4; mt++) {
                int m = wm * 64 + mt * 16;
                af[mt][0] = As[m + r][kk * 8 + c];
                af[mt][1] = As[m + r + 8][kk * 8 + c];
                af[mt][2] = As[m + r][kk * 8 + c + 4];
                af[mt][3] = As[m + r + 8][kk * 8 + c + 4];
            }
            #pragma unroll
            for (int nt = 0; nt < 4; nt++) {
                int n = wn * 32 + nt * 8 + r;
                bf[nt][0] = Bs[n][kk * 8 + c];
                bf[nt][1] = Bs[n][kk * 8 + c + 4];
            }
            #pragma unroll
            for (int mt = 0; mt < 4; mt++)
                #pragma unroll
                for (int nt = 0; nt < 4; nt++)
                    mma_tf32(acc[mt][nt], af[mt], bf[nt]);
        }
    }

    // epilogue: C[l][o] -> out[b][l][o]
    #pragma unroll
    for (int mt = 0; mt < 4; mt++) {
        int l = l0 + wm * 64 + mt * 16 + r;
        #pragma unroll
        for (int nt = 0; nt < 4; nt++) {
            int o = o0 + wn * 32 + nt * 8 + c * 2;
            float bo0 = bout[o], bo1 = bout[o + 1];
            float2 v0 = make_float2(acc[mt][nt][0] + bo0, acc[mt][nt][1] + bo1);
            float2 v1 = make_float2(acc[mt][nt][2] + bo0, acc[mt][nt][3] + bo1);
            *(float2*)&out[((size_t)b * LEN + l    ) * Dm + o] = v0;
            *(float2*)&out[((size_t)b * LEN + l + 8) * Dm + o] = v1;
        }
    }
}

// ---------------- launch ----------------
extern "C" void kernel_launch(void* const* d_in, const int* in_sizes, int n_in,
                              void* d_out, int out_size)
{
    (void)in_sizes; (void)n_in; (void)out_size;
    const float* u       = (const float*)d_in[0];
    const float* W_in    = (const float*)d_in[1];
    const float* b_in    = (const float*)d_in[2];
    const float* short_w = (const float*)d_in[3];
    const float* short_b = (const float*)d_in[4];
    const float* mlp_w1  = (const float*)d_in[5];
    const float* mlp_b1  = (const float*)d_in[6];
    const float* freq    = (const float*)d_in[7];
    const float* mlp_w2  = (const float*)d_in[8];
    const float* mlp_b2  = (const float*)d_in[9];
    const float* mlp_w3  = (const float*)d_in[10];
    const float* mlp_b3  = (const float*)d_in[11];
    const float* mlp_w4  = (const float*)d_in[12];
    const float* fbias   = (const float*)d_in[13];
    const float* W_out   = (const float*)d_in[14];
    const float* b_out   = (const float*)d_in[15];
    float* out = (float*)d_out;

    const int FFT_SMEM = NFFT * 2 * sizeof(float2);  // 131072
    cudaFuncSetAttribute(fftk_kernel,    cudaFuncAttributeMaxDynamicSharedMemorySize, FFT_SMEM);
    cudaFuncSetAttribute(fftconv_kernel, cudaFuncAttributeMaxDynamicSharedMemorySize, FFT_SMEM);

    filter_kernel<<<LEN, FORD>>>(mlp_w1, mlp_b1, freq, mlp_w2, mlp_b2, mlp_w3, mlp_b3, mlp_w4);
    fftk_kernel<<<Dm, 512, FFT_SMEM>>>();
    gemm1_tc<<<dim3(LEN/128, INNER/128, Bsz), 256>>>(u, W_in, b_in);
    shortconv_kernel<<<Bsz * Dm, 256>>>(short_w, short_b);
    fftconv_kernel<<<Bsz * (Dm/2), 512, FFT_SMEM>>>(fbias);
    gemm2_tc<<<dim3(LEN/128, Dm/128, Bsz), 256>>>(W_out, b_out, out);
}

// round 3
// speedup vs baseline: 1.5622x; 1.1107x over previous
#include <cuda_runtime.h>
#include <cstdint>

#define Bsz   16
#define LEN   4096
#define Dm    256
#define INNER 768
#define FORD  64
#define NFFT  8192
#define KHW   4104            // padded (NFFT/2 + 1)

// ---------------- scratch (static __device__, allowed) ----------------
__device__ float  g_X [(size_t)Bsz * INNER * LEN];   // (b, e, l)  201 MB
__device__ float  g_VG[(size_t)Bsz * Dm * LEN];      // v * x1     64 MB
__device__ float  g_X0[(size_t)Bsz * Dm * LEN];      // x0 gate    64 MB
__device__ float  g_OV[(size_t)Bsz * Dm * LEN];      // gated conv 64 MB
__device__ float  g_K [(size_t)Dm * LEN];            // filter     4 MB
__device__ float2 g_KH[(size_t)Dm * KHW];            // filter half-spectrum 8 MB

// ---------------- helpers ----------------
__device__ __forceinline__ uint32_t f2tf32(float x) {
    uint32_t r;
    asm("cvt.rna.tf32.f32 %0, %1;" : "=r"(r) : "f"(x));
    return r;
}

__device__ __forceinline__ void mma_tf32(float* c, const uint32_t* a, const uint32_t* b) {
    asm volatile(
        "mma.sync.aligned.m16n8k8.row.col.f32.tf32.tf32.f32 "
        "{%0,%1,%2,%3},{%4,%5,%6,%7},{%8,%9},{%0,%1,%2,%3};"
        : "+f"(c[0]), "+f"(c[1]), "+f"(c[2]), "+f"(c[3])
        : "r"(a[0]), "r"(a[1]), "r"(a[2]), "r"(a[3]), "r"(b[0]), "r"(b[1]));
}

// ---------------- implicit filter ----------------
__global__ void filter_kernel(const float* __restrict__ w1, const float* __restrict__ b1,
                              const float* __restrict__ freq,
                              const float* __restrict__ w2, const float* __restrict__ b2,
                              const float* __restrict__ w3, const float* __restrict__ b3,
                              const float* __restrict__ w4)
{
    __shared__ float ha[FORD];
    __shared__ float hb[FORD];
    int l = blockIdx.x;
    int j = threadIdx.x;   // 64 threads

    float t  = (float)l / (float)(LEN - 1);
    float a  = 1e-4f * 2.0f * 3.14159265358979323846f * (float)l / (float)LEN;
    float z0 = t, z1 = cosf(a), z2 = -sinf(a);

    float s1 = z0 * w1[j*3+0] + z1 * w1[j*3+1] + z2 * w1[j*3+2] + b1[j];
    ha[j] = sinf(freq[j] * s1);
    __syncthreads();

    float s2 = b2[j];
    #pragma unroll 8
    for (int i = 0; i < FORD; i++) s2 += ha[i] * w2[j*FORD + i];
    hb[j] = sinf(freq[j] * s2);
    __syncthreads();

    float s3 = b3[j];
    #pragma unroll 8
    for (int i = 0; i < FORD; i++) s3 += hb[i] * w3[j*FORD + i];
    float h3 = sinf(freq[j] * s3);
    __syncthreads();
    ha[j] = h3;
    __syncthreads();

    const float min_d = -4.605170185988091f / 1.5f;   // log(0.01)/1.5
    const float max_d = -4.605170185988091f / 0.3f;   // log(0.01)/0.3
    #pragma unroll
    for (int r = 0; r < 4; r++) {
        int d = j + r * FORD;
        float s4 = 0.f;
        #pragma unroll 8
        for (int i = 0; i < FORD; i++) s4 += ha[i] * w4[d*FORD + i];
        float delta = fabsf(min_d + (max_d - min_d) * (float)d / (float)(Dm - 1));
        g_K[(size_t)d * LEN + l] = s4 * expf(-t * delta);
    }
}

// ---------------- 8192-pt Stockham FFT: 6 radix-4 stages + 1 radix-2 ----------------
// Result ends in buf1 (same contract as the radix-2 version).
__device__ __forceinline__ void fft_stages(float2* buf0, float2* buf1, int tid, float sign)
{
    __syncthreads();
    float2* src = buf0;
    float2* dst = buf1;
    int h = NFFT / 2;        // 4096
    int s = 1, ls = 0;
    #pragma unroll 1
    for (int stage = 0; stage < 6; ++stage) {
        float ang = sign * 3.14159265358979323846f / (float)h;
        int hh = h >> 1;
        #pragma unroll
        for (int tt = 0; tt < 4; ++tt) {
            int idx = tid + tt * 512;          // 0..2047  (== q + s*p)
            int q = idx & (s - 1);
            int p = idx >> ls;
            float2 x0 = src[idx];
            float2 x1 = src[idx + s * hh];
            float2 x2 = src[idx + s * h];
            float2 x3 = src[idx + s * (h + hh)];
            float2 apc = make_float2(x0.x + x2.x, x0.y + x2.y);
            float2 amc = make_float2(x0.x - x2.x, x0.y - x2.y);
            float2 bpd = make_float2(x1.x + x3.x, x1.y + x3.y);
            float2 bmd = make_float2(x1.x - x3.x, x1.y - x3.y);
            float2 jv  = make_float2(-sign * bmd.y, sign * bmd.x);  // i*sign*(x1-x3)
            float sn, cs;
            __sincosf(ang * (float)p, &sn, &cs);                    // w
            float c2 = cs*cs - sn*sn, s2 = 2.f*cs*sn;               // w^2
            float c3 = c2*cs - s2*sn, s3 = c2*sn + s2*cs;           // w^3
            float2 t1 = make_float2(amc.x + jv.x, amc.y + jv.y);
            float2 t2 = make_float2(apc.x - bpd.x, apc.y - bpd.y);
            float2 t3 = make_float2(amc.x - jv.x, amc.y - jv.y);
            int ob = q + s * 4 * p;
            dst[ob]       = make_float2(apc.x + bpd.x, apc.y + bpd.y);
            dst[ob + s]   = make_float2(t1.x*cs - t1.y*sn, t1.x*sn + t1.y*cs);
            dst[ob + 2*s] = make_float2(t2.x*c2 - t2.y*s2, t2.x*s2 + t2.y*c2);
            dst[ob + 3*s] = make_float2(t3.x*c3 - t3.y*s3, t3.x*s3 + t3.y*c3);
        }
        __syncthreads();
        float2* tmp = src; src = dst; dst = tmp;
        h >>= 2; s <<= 2; ls += 2;
    }
    // final radix-2 stage: h=1, s=4096, twiddle = 1
    #pragma unroll
    for (int tt = 0; tt < 8; ++tt) {
        int idx = tid + tt * 512;              // 0..4095
        float2 a = src[idx];
        float2 b = src[idx + 4096];
        dst[idx]        = make_float2(a.x + b.x, a.y + b.y);
        dst[idx + 4096] = make_float2(a.x - b.x, a.y - b.y);
    }
    __syncthreads();
    // 7 stages total (odd) -> result in buf1
}

__global__ void fftk_kernel()
{
    extern __shared__ float2 sm[];
    float2* A  = sm;
    float2* Bb = sm + NFFT;
    int d = blockIdx.x;
    int tid = threadIdx.x;
    for (int i = tid; i < NFFT; i += 512) {
        float re = (i < LEN) ? g_K[(size_t)d * LEN + i] : 0.f;
        A[i] = make_float2(re, 0.f);
    }
    fft_stages(A, Bb, tid, -1.f);
    for (int i = tid; i <= NFFT / 2; i += 512)     // half spectrum (Hermitian: k real)
        g_KH[(size_t)d * KHW + i] = Bb[i];
}

// ---------------- GEMM1 (tensor cores, tf32):
//   g_X[b][e][l] = sum_k Win[e][k] * u[b][l][k] + b_in[e]
__global__ void __launch_bounds__(256, 1)
gemm1_tc(const float* __restrict__ u, const float* __restrict__ Win,
         const float* __restrict__ bin)
{
    __shared__ uint32_t As[128][36];   // [e][k]
    __shared__ uint32_t Bs[128][36];   // [l][k]
    int b  = blockIdx.z;
    int e0 = blockIdx.y * 128;
    int l0 = blockIdx.x * 128;
    int tid = threadIdx.x;
    int wid = tid >> 5, lane = tid & 31;
    int wm = wid & 1;
    int wn = wid >> 1;
    int r = lane >> 2, c = lane & 3;

    float acc[4][4][4];
    #pragma unroll
    for (int mt = 0; mt < 4; mt++)
        #pragma unroll
        for (int nt = 0; nt < 4; nt++)
            #pragma unroll
            for (int i = 0; i < 4; i++) acc[mt][nt][i] = 0.f;

    const float* ub = u + (size_t)b * LEN * Dm;

    for (int k0 = 0; k0 < Dm; k0 += 32) {
        __syncthreads();
        #pragma unroll
        for (int i = 0; i < 4; i++) {
            int f = tid + i * 256;
            int row = f >> 3, q = f & 7;
            float4 av = *(const float4*)&Win[(size_t)(e0 + row) * Dm + k0 + q * 4];
            uint4 at = make_uint4(f2tf32(av.x), f2tf32(av.y), f2tf32(av.z), f2tf32(av.w));
            *(uint4*)&As[row][q * 4] = at;
            float4 bv = *(const float4*)&ub[(size_t)(l0 + row) * Dm + k0 + q * 4];
            uint4 bt = make_uint4(f2tf32(bv.x), f2tf32(bv.y), f2tf32(bv.z), f2tf32(bv.w));
            *(uint4*)&Bs[row][q * 4] = bt;
        }
        __syncthreads();
        #pragma unroll
        for (int kk = 0; kk < 4; kk++) {
            uint32_t af[4][4], bf[4][2];
            #pragma unroll
            for (int mt = 0; mt < 4; mt++) {
                int m = wm * 64 + mt * 16;
                af[mt][0] = As[m + r][kk * 8 + c];
                af[mt][1] = As[m + r + 8][kk * 8 + c];
                af[mt][2] = As[m + r][kk * 8 + c + 4];
                af[mt][3] = As[m + r + 8][kk * 8 + c + 4];
            }
            #pragma unroll
            for (int nt = 0; nt < 4; nt++) {
                int n = wn * 32 + nt * 8 + r;
                bf[nt][0] = Bs[n][kk * 8 + c];
                bf[nt][1] = Bs[n][kk * 8 + c + 4];
            }
            #pragma unroll
            for (int mt = 0; mt < 4; mt++)
                #pragma unroll
                for (int nt = 0; nt < 4; nt++)
                    mma_tf32(acc[mt][nt], af[mt], bf[nt]);
        }
    }

    #pragma unroll
    for (int mt = 0; mt < 4; mt++) {
        int e = e0 + wm * 64 + mt * 16 + r;
        float be0 = bin[e], be8 = bin[e + 8];
        #pragma unroll
        for (int nt = 0; nt < 4; nt++) {
            int l = l0 + wn * 32 + nt * 8 + c * 2;
            float2 v0 = make_float2(acc[mt][nt][0] + be0, acc[mt][nt][1] + be0);
            float2 v1 = make_float2(acc[mt][nt][2] + be8, acc[mt][nt][3] + be8);
            *(float2*)&g_X[((size_t)b * INNER + e    ) * LEN + l] = v0;
            *(float2*)&g_X[((size_t)b * INNER + e + 8) * LEN + l] = v1;
        }
    }
}

// ---------------- short depthwise conv + gating ----------------
__global__ void shortconv_kernel(const float* __restrict__ sw, const float* __restrict__ sb)
{
    int bd = blockIdx.x;
    int b = bd >> 8, d = bd & 255;
    const float* xr0 = &g_X[((size_t)b * INNER + d        ) * LEN];
    const float* xr1 = &g_X[((size_t)b * INNER + Dm   + d ) * LEN];
    const float* xrv = &g_X[((size_t)b * INNER + 2*Dm + d ) * LEN];
    int c0 = d, c1 = Dm + d, c2 = 2 * Dm + d;
    float w00 = sw[c0*3], w01 = sw[c0*3+1], w02 = sw[c0*3+2];
    float w10 = sw[c1*3], w11 = sw[c1*3+1], w12 = sw[c1*3+2];
    float w20 = sw[c2*3], w21 = sw[c2*3+1], w22 = sw[c2*3+2];
    float bb0 = sb[c0], bb1 = sb[c1], bb2 = sb[c2];
    float* x0o = &g_X0[((size_t)b * Dm + d) * LEN];
    float* vgo = &g_VG[((size_t)b * Dm + d) * LEN];
    for (int l = threadIdx.x; l < LEN; l += blockDim.x) {
        float a2 = (l >= 2) ? xr0[l-2] : 0.f;
        float a1 = (l >= 1) ? xr0[l-1] : 0.f;
        float a0 = xr0[l];
        float ux0 = w00*a2 + w01*a1 + w02*a0 + bb0;
        float b2v = (l >= 2) ? xr1[l-2] : 0.f;
        float b1v = (l >= 1) ? xr1[l-1] : 0.f;
        float b0v = xr1[l];
        float ux1 = w10*b2v + w11*b1v + w12*b0v + bb1;
        float c2v = (l >= 2) ? xrv[l-2] : 0.f;
        float c1v = (l >= 1) ? xrv[l-1] : 0.f;
        float c0v = xrv[l];
        float uv  = w20*c2v + w21*c1v + w22*c0v + bb2;
        x0o[l] = ux0;
        vgo[l] = uv * ux1;
    }
}

// ---------------- FFT long conv: two real channels per complex FFT ----------------
__global__ void fftconv_kernel(const float* __restrict__ fbias)
{
    extern __shared__ float2 sm[];
    float2* A  = sm;
    float2* Bb = sm + NFFT;
    int blk = blockIdx.x;                    // 2048
    int b = blk >> 7, dp = blk & 127;
    int d0 = dp * 2, d1 = d0 + 1;
    int tid = threadIdx.x;

    const float* vg0 = &g_VG[((size_t)b * Dm + d0) * LEN];
    const float* vg1 = vg0 + LEN;
    for (int i = tid; i < NFFT; i += 512) {
        float re = (i < LEN) ? vg0[i] : 0.f;
        float im = (i < LEN) ? vg1[i] : 0.f;
        A[i] = make_float2(re, im);
    }
    fft_stages(A, Bb, tid, -1.f);            // spectrum Z in Bb

    // pointwise multiply using Hermitian pairing: process (i, N-i) together
    const float2* KH0 = &g_KH[(size_t)d0 * KHW];
    const float2* KH1 = KH0 + KHW;
    for (int i = tid; i <= NFFT / 2; i += 512) {
        int jj = (NFFT - i) & (NFFT - 1);
        float2 z1 = Bb[i], z2 = Bb[jj];
        // V0 = even part (spectrum of ch d0), V1 = odd part (ch d1)
        float2 V0 = make_float2(0.5f * (z1.x + z2.x), 0.5f * (z1.y - z2.y));
        float2 V1 = make_float2(0.5f * (z1.y + z2.y), 0.5f * (z2.x - z1.x));
        float2 k0 = KH0[i], k1 = KH1[i];
        float2 P = make_float2(V0.x * k0.x - V0.y * k0.y, V0.x * k0.y + V0.y * k0.x);
        float2 Q = make_float2(V1.x * k1.x - V1.y * k1.y, V1.x * k1.y + V1.y * k1.x);
        A[i]  = make_float2(P.x - Q.y, P.y + Q.x);        // W[i]  = P + iQ
        A[jj] = make_float2(P.x + Q.y, Q.x - P.y);        // W[N-i] = conj(P) + i*conj(Q)
    }
    fft_stages(A, Bb, tid, +1.f);            // y0 + i*y1 in Bb (unscaled)

    const float inv = 1.f / (float)NFFT;
    float bias0 = fbias[d0], bias1 = fbias[d1];
    float* ov0 = &g_OV[((size_t)b * Dm + d0) * LEN];
    float* ov1 = ov0 + LEN;
    const float* x00 = &g_X0[((size_t)b * Dm + d0) * LEN];
    const float* x01 = x00 + LEN;
    for (int l = tid; l < LEN; l += 512) {
        float y0 = Bb[l].x * inv;
        float y1 = Bb[l].y * inv;
        ov0[l] = (y0 + vg0[l] * bias0) * x00[l];
        ov1[l] = (y1 + vg1[l] * bias1) * x01[l];
    }
}

// ---------------- GEMM2 (tensor cores, tf32):
//   out[b][l][o] = sum_k g_OV[b][k][l] * Wout[o][k] + b_out[o]
__global__ void __launch_bounds__(256, 1)
gemm2_tc(const float* __restrict__ Wout, const float* __restrict__ bout,
         float* __restrict__ out)
{
    __shared__ uint32_t As[128][36];   // [l][k]
    __shared__ uint32_t Bs[128][36];   // [o][k]
    int b  = blockIdx.z;
    int l0 = blockIdx.x * 128;
    int o0 = blockIdx.y * 128;
    int tid = threadIdx.x;
    int wid = tid >> 5, lane = tid & 31;
    int wm = wid & 1;
    int wn = wid >> 1;
    int r = lane >> 2, c = lane & 3;

    float acc[4][4][4];
    #pragma unroll
    for (int mt = 0; mt < 4; mt++)
        #pragma unroll
        for (int nt = 0; nt < 4; nt++)
            #pragma unroll
            for (int i = 0; i < 4; i++) acc[mt][nt][i] = 0.f;

    const float* ovb = &g_OV[(size_t)b * Dm * LEN];

    int ka = tid >> 3;
    int fa = tid & 7;
    for (int k0 = 0; k0 < Dm; k0 += 32) {
        __syncthreads();
        #pragma unroll
        for (int i = 0; i < 4; i++) {
            int f = fa + i * 8;
            int lq = f * 4;
            float4 av = *(const float4*)&ovb[(size_t)(k0 + ka) * LEN + l0 + lq];
            As[lq + 0][ka] = f2tf32(av.x);
            As[lq + 1][ka] = f2tf32(av.y);
            As[lq + 2][ka] = f2tf32(av.z);
            As[lq + 3][ka] = f2tf32(av.w);
        }
        #pragma unroll
        for (int i = 0; i < 4; i++) {
            int f = tid + i * 256;
            int row = f >> 3, q = f & 7;
            float4 bv = *(const float4*)&Wout[(size_t)(o0 + row) * Dm + k0 + q * 4];
            uint4 bt = make_uint4(f2tf32(bv.x), f2tf32(bv.y), f2tf32(bv.z), f2tf32(bv.w));
            *(uint4*)&Bs[row][q * 4] = bt;
        }
        __syncthreads();
        #pragma unroll
        for (int kk = 0; kk < 4; kk++) {
            uint32_t af[4][4], bf[4][2];
            #pragma unroll
            for (int mt = 0; mt < 4; mt++) {
                int m = wm * 64 + mt * 16;
                af[mt][0] = As[m + r][kk * 8 + c];
                af[mt][1] = As[m + r + 8][kk * 8 + c];
                af[mt][2] = As[m + r][kk * 8 + c + 4];
                af[mt][3] = As[m + r + 8][kk * 8 + c + 4];
            }
            #pragma unroll
            for (int nt = 0; nt < 4; nt++) {
                int n = wn * 32 + nt * 8 + r;
                bf[nt][0] = Bs[n][kk * 8 + c];
                bf[nt][1] = Bs[n][kk * 8 + c + 4];
            }
            #pragma unroll
            for (int mt = 0; mt < 4; mt++)
                #pragma unroll
                for (int nt = 0; nt < 4; nt++)
                    mma_tf32(acc[mt][nt], af[mt], bf[nt]);
        }
    }

    #pragma unroll
    for (int mt = 0; mt < 4; mt++) {
        int l = l0 + wm * 64 + mt * 16 + r;
        #pragma unroll
        for (int nt = 0; nt < 4; nt++) {
            int o = o0 + wn * 32 + nt * 8 + c * 2;
            float bo0 = bout[o], bo1 = bout[o + 1];
            float2 v0 = make_float2(acc[mt][nt][0] + bo0, acc[mt][nt][1] + bo1);
            float2 v1 = make_float2(acc[mt][nt][2] + bo0, acc[mt][nt][3] + bo1);
            *(float2*)&out[((size_t)b * LEN + l    ) * Dm + o] = v0;
            *(float2*)&out[((size_t)b * LEN + l + 8) * Dm + o] = v1;
        }
    }
}

// ---------------- launch ----------------
extern "C" void kernel_launch(void* const* d_in, const int* in_sizes, int n_in,
                              void* d_out, int out_size)
{
    (void)in_sizes; (void)n_in; (void)out_size;
    const float* u       = (const float*)d_in[0];
    const float* W_in    = (const float*)d_in[1];
    const float* b_in    = (const float*)d_in[2];
    const float* short_w = (const float*)d_in[3];
    const float* short_b = (const float*)d_in[4];
    const float* mlp_w1  = (const float*)d_in[5];
    const float* mlp_b1  = (const float*)d_in[6];
    const float* freq    = (const float*)d_in[7];
    const float* mlp_w2  = (const float*)d_in[8];
    const float* mlp_b2  = (const float*)d_in[9];
    const float* mlp_w3  = (const float*)d_in[10];
    const float* mlp_b3  = (const float*)d_in[11];
    const float* mlp_w4  = (const float*)d_in[12];
    const float* fbias   = (const float*)d_in[13];
    const float* W_out   = (const float*)d_in[14];
    const float* b_out   = (const float*)d_in[15];
    float* out = (float*)d_out;

    const int FFT_SMEM = NFFT * 2 * sizeof(float2);  // 131072
    cudaFuncSetAttribute(fftk_kernel,    cudaFuncAttributeMaxDynamicSharedMemorySize, FFT_SMEM);
    cudaFuncSetAttribute(fftconv_kernel, cudaFuncAttributeMaxDynamicSharedMemorySize, FFT_SMEM);

    filter_kernel<<<LEN, FORD>>>(mlp_w1, mlp_b1, freq, mlp_w2, mlp_b2, mlp_w3, mlp_b3, mlp_w4);
    fftk_kernel<<<Dm, 512, FFT_SMEM>>>();
    gemm1_tc<<<dim3(LEN/128, INNER/128, Bsz), 256>>>(u, W_in, b_in);
    shortconv_kernel<<<Bsz * Dm, 256>>>(short_w, short_b);
    fftconv_kernel<<<Bsz * (Dm/2), 512, FFT_SMEM>>>(fbias);
    gemm2_tc<<<dim3(LEN/128, Dm/128, Bsz), 256>>>(W_out, b_out, out);
}